// round 2
// baseline (speedup 1.0000x reference)
#include <cuda_runtime.h>

// ---------------------------------------------------------------------------
// GCN(D=256) x2 + MLP head, algebraically folded:
//   out = A( A (X Wfold) + c1*1 ) + bc
// with Wfold = W1^T W2^T Wm1^T Wm2^T  [256 x 5],
//      c1 = b1 @ (W2^T Wm1^T Wm2^T),  bc = Wm2(Wm1 b2 + bm1) + bm2
// A = D^{-1/2} (Adj + I) D^{-1/2}; dinv factored out of edge kernels:
//   (A v)[i] = dinv[i] * ( sum_{edges s->i} dinv[s] v[s] + dinv[i] v[i] )
// ---------------------------------------------------------------------------

#define Dd 256
#define Hh 128
#define Cc 5
#define Ss 8           // padded row stride (32B aligned rows -> 1 L2 sector)
#define NMAX 100352

__device__ float g_deg[NMAX];        // degree, then dinv in-place
__device__ float g_bufA[NMAX * Ss];  // z' (=dinv*z), then q (=dinv*pp)
__device__ float g_bufB[NMAX * Ss];  // edge-sum accumulator (both passes)
__device__ float g_W[Dd * Cc];       // folded 256x5 weight
__device__ float g_c1[Cc];
__device__ float g_bc[Cc];

__global__ void init_kernel(int n) {
    int i = blockIdx.x * blockDim.x + threadIdx.x;
    if (i < n) {
        g_deg[i] = 1.0f;  // self-loop contributes 1 to degree
        float4 z = make_float4(0.f, 0.f, 0.f, 0.f);
        ((float4*)g_bufB)[i * 2 + 0] = z;
        ((float4*)g_bufB)[i * 2 + 1] = z;
    }
}

__global__ void deg_kernel(const int* __restrict__ dst, int E) {
    int e = blockIdx.x * blockDim.x + threadIdx.x;
    if (e < E) atomicAdd(&g_deg[__ldg(dst + e)], 1.0f);
}

__global__ void dinv_kernel(int n) {
    int i = blockIdx.x * blockDim.x + threadIdx.x;
    if (i < n) g_deg[i] = rsqrtf(g_deg[i]);  // deg >= 1 always
}

// Single-block kernel: fold all weights into g_W [256x5], g_c1, g_bc.
__global__ void fold_kernel(const float* __restrict__ W1, const float* __restrict__ b1,
                            const float* __restrict__ W2, const float* __restrict__ b2,
                            const float* __restrict__ Wm1, const float* __restrict__ bm1,
                            const float* __restrict__ Wm2, const float* __restrict__ bm2) {
    __shared__ float sA[Dd * Cc];  // M1[m][c] = sum_h Wm1[h,m]*Wm2[c,h]
    __shared__ float sB[Dd * Cc];  // WcT[o][c] = sum_m W2[m,o]*M1[m][c]
    __shared__ float st[Hh];
    int tid = threadIdx.x;  // 256 threads

    {   // M1[tid][c] = sum_h Wm1[h, tid] * Wm2[c, h]
        float acc[Cc] = {};
        for (int h = 0; h < Hh; ++h) {
            float a = Wm1[h * Dd + tid];
            #pragma unroll
            for (int c = 0; c < Cc; ++c) acc[c] += a * Wm2[c * Hh + h];
        }
        #pragma unroll
        for (int c = 0; c < Cc; ++c) sA[tid * Cc + c] = acc[c];
    }
    __syncthreads();
    {   // WcT[tid][c] = sum_m W2[m, tid] * M1[m][c]
        float acc[Cc] = {};
        for (int m = 0; m < Dd; ++m) {
            float a = W2[m * Dd + tid];
            #pragma unroll
            for (int c = 0; c < Cc; ++c) acc[c] += a * sA[m * Cc + c];
        }
        #pragma unroll
        for (int c = 0; c < Cc; ++c) sB[tid * Cc + c] = acc[c];
    }
    __syncthreads();
    {   // Wfold[tid][c] = sum_o W1[o, tid] * WcT[o][c]
        float acc[Cc] = {};
        for (int o = 0; o < Dd; ++o) {
            float a = W1[o * Dd + tid];
            #pragma unroll
            for (int c = 0; c < Cc; ++c) acc[c] += a * sB[o * Cc + c];
        }
        #pragma unroll
        for (int c = 0; c < Cc; ++c) g_W[tid * Cc + c] = acc[c];
    }
    // t[h] = Wm1[h,:].b2 + bm1[h]
    if (tid < Hh) {
        float s = bm1[tid];
        for (int d = 0; d < Dd; ++d) s += Wm1[tid * Dd + d] * b2[d];
        st[tid] = s;
    }
    __syncthreads();
    if (tid < Cc) {
        float s1 = 0.f;
        for (int d = 0; d < Dd; ++d) s1 += b1[d] * sB[d * Cc + tid];
        g_c1[tid] = s1;
        float s2 = bm2[tid];
        for (int h = 0; h < Hh; ++h) s2 += Wm2[tid * Hh + h] * st[h];
        g_bc[tid] = s2;
    }
}

// z' = dinv * (X @ Wfold): one warp per node, float4 loads of the 1KB row.
__global__ void gemv_kernel(const float* __restrict__ x, int n) {
    __shared__ float sW[Dd * Cc];
    for (int i = threadIdx.x; i < Dd * Cc; i += blockDim.x) sW[i] = g_W[i];
    __syncthreads();
    int gw = (blockIdx.x * blockDim.x + threadIdx.x) >> 5;
    int lane = threadIdx.x & 31;
    if (gw >= n) return;
    const float4* xr = (const float4*)x + (size_t)gw * (Dd / 4);
    float a0 = 0.f, a1 = 0.f, a2 = 0.f, a3 = 0.f, a4 = 0.f;
    #pragma unroll
    for (int it = 0; it < 2; ++it) {
        float4 v = xr[it * 32 + lane];
        const float* w = &sW[(it * 32 + lane) * 4 * Cc];
        a0 += v.x * w[0] + v.y * w[5] + v.z * w[10] + v.w * w[15];
        a1 += v.x * w[1] + v.y * w[6] + v.z * w[11] + v.w * w[16];
        a2 += v.x * w[2] + v.y * w[7] + v.z * w[12] + v.w * w[17];
        a3 += v.x * w[3] + v.y * w[8] + v.z * w[13] + v.w * w[18];
        a4 += v.x * w[4] + v.y * w[9] + v.z * w[14] + v.w * w[19];
    }
    #pragma unroll
    for (int off = 16; off; off >>= 1) {
        a0 += __shfl_xor_sync(0xFFFFFFFFu, a0, off);
        a1 += __shfl_xor_sync(0xFFFFFFFFu, a1, off);
        a2 += __shfl_xor_sync(0xFFFFFFFFu, a2, off);
        a3 += __shfl_xor_sync(0xFFFFFFFFu, a3, off);
        a4 += __shfl_xor_sync(0xFFFFFFFFu, a4, off);
    }
    if (lane == 0) {
        float w = g_deg[gw];  // dinv
        float* o = &g_bufA[(size_t)gw * Ss];
        o[0] = w * a0; o[1] = w * a1; o[2] = w * a2; o[3] = w * a3; o[4] = w * a4;
    }
}

// Edge pass: bufB[dst] += bufA[src]  (5 channels, no weights needed)
__global__ void agg_kernel(const int* __restrict__ src, const int* __restrict__ dst, int E) {
    int e = blockIdx.x * blockDim.x + threadIdx.x;
    if (e >= E) return;
    int s = __ldg(src + e);
    int d = __ldg(dst + e);
    const float* vs = &g_bufA[(size_t)s * Ss];
    float4 a = *(const float4*)vs;
    float a4 = vs[4];
    float* vd = &g_bufB[(size_t)d * Ss];
    atomicAdd(vd + 0, a.x);
    atomicAdd(vd + 1, a.y);
    atomicAdd(vd + 2, a.z);
    atomicAdd(vd + 3, a.w);
    atomicAdd(vd + 4, a4);
}

// After pass 1: pp = dinv*(edge_sum + z') + c1 ;  q = dinv*pp -> bufA; reset bufB.
__global__ void fin1_kernel(int n) {
    int i = blockIdx.x * blockDim.x + threadIdx.x;
    if (i >= n) return;
    float w = g_deg[i];
    #pragma unroll
    for (int c = 0; c < Cc; ++c) {
        float pp = w * (g_bufB[i * Ss + c] + g_bufA[i * Ss + c]) + g_c1[c];
        g_bufA[i * Ss + c] = w * pp;
        g_bufB[i * Ss + c] = 0.f;
    }
}

// After pass 2: out = dinv*(edge_sum + q) + bc
__global__ void fin2_kernel(float* __restrict__ out, int n) {
    int i = blockIdx.x * blockDim.x + threadIdx.x;
    if (i >= n) return;
    float w = g_deg[i];
    #pragma unroll
    for (int c = 0; c < Cc; ++c) {
        out[i * Cc + c] = w * (g_bufB[i * Ss + c] + g_bufA[i * Ss + c]) + g_bc[c];
    }
}

extern "C" void kernel_launch(void* const* d_in, const int* in_sizes, int n_in,
                              void* d_out, int out_size) {
    const float* x   = (const float*)d_in[0];
    const int*   ei  = (const int*)d_in[1];
    const float* W1  = (const float*)d_in[2];
    const float* b1  = (const float*)d_in[3];
    const float* W2  = (const float*)d_in[4];
    const float* b2  = (const float*)d_in[5];
    const float* Wm1 = (const float*)d_in[6];
    const float* bm1 = (const float*)d_in[7];
    const float* Wm2 = (const float*)d_in[8];
    const float* bm2 = (const float*)d_in[9];
    float* out = (float*)d_out;

    int n = in_sizes[0] / Dd;
    int E = in_sizes[1] / 2;
    const int* src = ei;
    const int* dst = ei + E;

    int nb = (n + 255) / 256;
    int eb = (E + 255) / 256;
    int gb = (n * 32 + 255) / 256;  // warp-per-node GEMV

    init_kernel<<<nb, 256>>>(n);
    deg_kernel<<<eb, 256>>>(dst, E);
    dinv_kernel<<<nb, 256>>>(n);
    fold_kernel<<<1, 256>>>(W1, b1, W2, b2, Wm1, bm1, Wm2, bm2);
    gemv_kernel<<<gb, 256>>>(x, n);
    agg_kernel<<<eb, 256>>>(src, dst, E);   // pass 1
    fin1_kernel<<<nb, 256>>>(n);
    agg_kernel<<<eb, 256>>>(src, dst, E);   // pass 2
    fin2_kernel<<<nb, 256>>>(out, n);
}

// round 3
// speedup vs baseline: 1.8271x; 1.8271x over previous
#include <cuda_runtime.h>

// ---------------------------------------------------------------------------
// GCN(D=256) x2 + MLP head, algebraically folded:
//   out = A( A (X Wfold) + c1*1 ) + bc
// with Wfold = W1^T W2^T Wm1^T Wm2^T  [256 x 5],
//      c1 = b1 @ (W2^T Wm1^T Wm2^T),  bc = Wm2(Wm1 b2 + bm1) + bm2
// A = D^{-1/2} (Adj + I) D^{-1/2}; dinv factored out of edge kernels.
// R3: fold parallelized across SMs (3 stage kernels + bias kernel),
//     edge aggregation uses red.global.add.v4.f32 (2 RED ops/edge vs 5).
// ---------------------------------------------------------------------------

#define Dd 256
#define Hh 128
#define Cc 5
#define Ss 8           // padded row stride (32B aligned rows -> 1 L2 sector)
#define NMAX 100352

__device__ float g_deg[NMAX];        // degree, then dinv in-place
__device__ float g_bufA[NMAX * Ss];  // z' (=dinv*z), then q (=dinv*pp)
__device__ float g_bufB[NMAX * Ss];  // edge-sum accumulator (both passes)
__device__ float g_M1[Dd * Cc];      // stage-1 intermediate
__device__ float g_WcT[Dd * Cc];     // stage-2 intermediate
__device__ float g_W[Dd * Cc];       // folded 256x5 weight
__device__ float g_c1[Cc];
__device__ float g_bc[Cc];

__global__ void init_kernel(int n) {
    int i = blockIdx.x * blockDim.x + threadIdx.x;
    if (i < n) {
        g_deg[i] = 1.0f;  // self-loop contributes 1 to degree
        float4 z = make_float4(0.f, 0.f, 0.f, 0.f);
        ((float4*)g_bufB)[i * 2 + 0] = z;
        ((float4*)g_bufB)[i * 2 + 1] = z;
    }
    if (i < Dd * Cc) {
        g_M1[i] = 0.f; g_WcT[i] = 0.f; g_W[i] = 0.f;
    }
}

__global__ void deg_kernel(const int* __restrict__ dst, int E) {
    int e = blockIdx.x * blockDim.x + threadIdx.x;
    if (e < E) atomicAdd(&g_deg[__ldg(dst + e)], 1.0f);
}

__global__ void dinv_kernel(int n) {
    int i = blockIdx.x * blockDim.x + threadIdx.x;
    if (i < n) g_deg[i] = rsqrtf(g_deg[i]);  // deg >= 1 always
}

// Generic fold stage: Out[t][c] += sum_{k in block chunk} A[k*Dd + t] * B[k][c]
// A is [kdim x Dd] row-major (coalesced over t), B is kdim x Cc.
// If bT != 0, B is stored [Cc x kdim] (i.e. B[c*kdim + k]).
// gridDim.x blocks partition kdim; results combined via atomicAdd.
__global__ void stage_kernel(const float* __restrict__ A, const float* __restrict__ B,
                             float* __restrict__ Out, int kdim, int bT) {
    __shared__ float sB[Dd * Cc];
    int tid = threadIdx.x;  // 256 threads
    for (int i = tid; i < kdim * Cc; i += blockDim.x) {
        int k = i / Cc, c = i - k * Cc;
        sB[i] = bT ? B[c * kdim + k] : B[i];
    }
    __syncthreads();
    int chunk = kdim / gridDim.x;
    int k0 = blockIdx.x * chunk;
    float acc[Cc] = {};
    for (int k = k0; k < k0 + chunk; ++k) {
        float a = A[k * Dd + tid];
        #pragma unroll
        for (int c = 0; c < Cc; ++c) acc[c] += a * sB[k * Cc + c];
    }
    #pragma unroll
    for (int c = 0; c < Cc; ++c) atomicAdd(&Out[tid * Cc + c], acc[c]);
}

// Small bias folds: c1 = b1 @ WcT ; bc = Wm2 (Wm1 b2 + bm1) + bm2
__global__ void bias_kernel(const float* __restrict__ b1, const float* __restrict__ b2,
                            const float* __restrict__ Wm1, const float* __restrict__ bm1,
                            const float* __restrict__ Wm2, const float* __restrict__ bm2) {
    __shared__ float st[Hh];
    int tid = threadIdx.x, w = tid >> 5, lane = tid & 31;  // 256 thr, 8 warps
    // t[h] = Wm1[h,:].b2 + bm1[h]; warp w handles h = w*16 .. w*16+15
    for (int i = 0; i < 16; ++i) {
        int h = w * 16 + i;
        float s = 0.f;
        for (int d = lane; d < Dd; d += 32) s += Wm1[h * Dd + d] * b2[d];
        #pragma unroll
        for (int off = 16; off; off >>= 1) s += __shfl_xor_sync(0xFFFFFFFFu, s, off);
        if (lane == 0) st[h] = s + bm1[h];
    }
    __syncthreads();
    if (w < Cc) {
        float s1 = 0.f;
        for (int d = lane; d < Dd; d += 32) s1 += b1[d] * g_WcT[d * Cc + w];
        #pragma unroll
        for (int off = 16; off; off >>= 1) s1 += __shfl_xor_sync(0xFFFFFFFFu, s1, off);
        if (lane == 0) g_c1[w] = s1;
        float s2 = 0.f;
        for (int h = lane; h < Hh; h += 32) s2 += Wm2[w * Hh + h] * st[h];
        #pragma unroll
        for (int off = 16; off; off >>= 1) s2 += __shfl_xor_sync(0xFFFFFFFFu, s2, off);
        if (lane == 0) g_bc[w] = s2 + bm2[w];
    }
}

// z' = dinv * (X @ Wfold): one warp per node, float4 loads of the 1KB row.
__global__ void gemv_kernel(const float* __restrict__ x, int n) {
    __shared__ float sW[Dd * Cc];
    for (int i = threadIdx.x; i < Dd * Cc; i += blockDim.x) sW[i] = g_W[i];
    __syncthreads();
    int gw = (blockIdx.x * blockDim.x + threadIdx.x) >> 5;
    int lane = threadIdx.x & 31;
    if (gw >= n) return;
    const float4* xr = (const float4*)x + (size_t)gw * (Dd / 4);
    float a0 = 0.f, a1 = 0.f, a2 = 0.f, a3 = 0.f, a4 = 0.f;
    #pragma unroll
    for (int it = 0; it < 2; ++it) {
        float4 v = xr[it * 32 + lane];
        const float* w = &sW[(it * 32 + lane) * 4 * Cc];
        a0 += v.x * w[0] + v.y * w[5] + v.z * w[10] + v.w * w[15];
        a1 += v.x * w[1] + v.y * w[6] + v.z * w[11] + v.w * w[16];
        a2 += v.x * w[2] + v.y * w[7] + v.z * w[12] + v.w * w[17];
        a3 += v.x * w[3] + v.y * w[8] + v.z * w[13] + v.w * w[18];
        a4 += v.x * w[4] + v.y * w[9] + v.z * w[14] + v.w * w[19];
    }
    #pragma unroll
    for (int off = 16; off; off >>= 1) {
        a0 += __shfl_xor_sync(0xFFFFFFFFu, a0, off);
        a1 += __shfl_xor_sync(0xFFFFFFFFu, a1, off);
        a2 += __shfl_xor_sync(0xFFFFFFFFu, a2, off);
        a3 += __shfl_xor_sync(0xFFFFFFFFu, a3, off);
        a4 += __shfl_xor_sync(0xFFFFFFFFu, a4, off);
    }
    if (lane == 0) {
        float w = g_deg[gw];  // dinv
        float* o = &g_bufA[(size_t)gw * Ss];
        o[0] = w * a0; o[1] = w * a1; o[2] = w * a2; o[3] = w * a3; o[4] = w * a4;
    }
}

// Edge pass: bufB[dst] += bufA[src]  (5 channels: one v4 RED + one scalar RED)
__global__ void agg_kernel(const int* __restrict__ src, const int* __restrict__ dst, int E) {
    int e = blockIdx.x * blockDim.x + threadIdx.x;
    if (e >= E) return;
    int s = __ldg(src + e);
    int d = __ldg(dst + e);
    const float* vs = &g_bufA[(size_t)s * Ss];
    float4 a = *(const float4*)vs;
    float a4 = vs[4];
    float* vd = &g_bufB[(size_t)d * Ss];
    unsigned long long gp = __cvta_generic_to_global(vd);
    asm volatile("red.global.add.v4.f32 [%0], {%1, %2, %3, %4};"
                 :: "l"(gp), "f"(a.x), "f"(a.y), "f"(a.z), "f"(a.w) : "memory");
    atomicAdd(vd + 4, a4);
}

// After pass 1: pp = dinv*(edge_sum + z') + c1 ;  q = dinv*pp -> bufA; reset bufB.
__global__ void fin1_kernel(int n) {
    int i = blockIdx.x * blockDim.x + threadIdx.x;
    if (i >= n) return;
    float w = g_deg[i];
    #pragma unroll
    for (int c = 0; c < Cc; ++c) {
        float pp = w * (g_bufB[i * Ss + c] + g_bufA[i * Ss + c]) + g_c1[c];
        g_bufA[i * Ss + c] = w * pp;
        g_bufB[i * Ss + c] = 0.f;
    }
}

// After pass 2: out = dinv*(edge_sum + q) + bc
__global__ void fin2_kernel(float* __restrict__ out, int n) {
    int i = blockIdx.x * blockDim.x + threadIdx.x;
    if (i >= n) return;
    float w = g_deg[i];
    #pragma unroll
    for (int c = 0; c < Cc; ++c) {
        out[i * Cc + c] = w * (g_bufB[i * Ss + c] + g_bufA[i * Ss + c]) + g_bc[c];
    }
}

extern "C" void kernel_launch(void* const* d_in, const int* in_sizes, int n_in,
                              void* d_out, int out_size) {
    const float* x   = (const float*)d_in[0];
    const int*   ei  = (const int*)d_in[1];
    const float* W1  = (const float*)d_in[2];
    const float* b1  = (const float*)d_in[3];
    const float* W2  = (const float*)d_in[4];
    const float* b2  = (const float*)d_in[5];
    const float* Wm1 = (const float*)d_in[6];
    const float* bm1 = (const float*)d_in[7];
    const float* Wm2 = (const float*)d_in[8];
    const float* bm2 = (const float*)d_in[9];
    float* out = (float*)d_out;

    int n = in_sizes[0] / Dd;
    int E = in_sizes[1] / 2;
    const int* src = ei;
    const int* dst = ei + E;

    int nb = (n + 255) / 256;
    int eb = (E + 255) / 256;
    int gb = (n * 32 + 255) / 256;  // warp-per-node GEMV

    float* pM1  = nullptr; cudaGetSymbolAddress((void**)&pM1,  g_M1);
    float* pWcT = nullptr; cudaGetSymbolAddress((void**)&pWcT, g_WcT);
    float* pW   = nullptr; cudaGetSymbolAddress((void**)&pW,   g_W);

    init_kernel<<<nb, 256>>>(n);
    deg_kernel<<<eb, 256>>>(dst, E);
    dinv_kernel<<<nb, 256>>>(n);
    // fold: M1 = Wm1^T Wm2^T ; WcT = W2^T M1 ; Wfold = W1^T WcT
    stage_kernel<<<8, 256>>>(Wm1, Wm2, pM1, Hh, 1);   // B transposed [Cc x Hh]
    stage_kernel<<<16, 256>>>(W2, pM1, pWcT, Dd, 0);
    stage_kernel<<<16, 256>>>(W1, pWcT, pW, Dd, 0);
    bias_kernel<<<1, 256>>>(b1, b2, Wm1, bm1, Wm2, bm2);
    gemv_kernel<<<gb, 256>>>(x, n);
    agg_kernel<<<eb, 256>>>(src, dst, E);   // pass 1
    fin1_kernel<<<nb, 256>>>(n);
    agg_kernel<<<eb, 256>>>(src, dst, E);   // pass 2
    fin2_kernel<<<nb, 256>>>(out, n);
}